// round 13
// baseline (speedup 1.0000x reference)
#include <cuda_runtime.h>
#include <cstdint>

#define S_DIM 8192
#define E_DIM 512
#define B_DIM 8
#define SE_DIM (S_DIM * E_DIM)
#define M_TOTAL 65536
#define K_DIM 512
#define N_DIM 512
#define GRID_P 152
#define NTILE 1024            // 512 m-tiles x 2 N-halves

#if defined(__CUDA_ARCH_FEAT_SM103_ALL) || defined(__CUDA_ARCH_FEAT_SM100_ALL) || \
    defined(__CUDA_ARCH_FEAT_SM101_ALL) || defined(__CUDA_ARCH_FEAT_SM110_ALL)
#define HAS_TCGEN05 1
#else
#define HAS_TCGEN05 0
#endif

// W scratch, CHUNK-MAJOR + PRE-SWIZZLED:
//   g_W32 byte (c*65536 + sw128(n*128 + j*4)) = tf32(W[n][c*32 + j])
// Rows [0,256) / [256,512) of each chunk block are contiguous 32KB slices.
__device__ float g_W32[(size_t)N_DIM * K_DIM];

// ---------------------------------------------------------------------------
__device__ __forceinline__ float to_tf32(float v) {
    float r;
    asm("cvt.rna.tf32.f32 %0, %1;" : "=f"(r) : "f"(v));
    return r;
}

// XU-free cos + tf32 rounding (fma/alu pipes only). Valid for |t| < ~1e5.
__device__ __forceinline__ uint32_t cos_tf32_bits(float t) {
    const float MAGIC = 12582912.0f;               // 1.5 * 2^23
    float g = fmaf(t, 0.63661977236758134f, MAGIC);
    int q = __float_as_int(g);
    float qf = g - MAGIC;
    float r = fmaf(qf, -1.57079637050628662109375f, t);
    r = fmaf(qf, 4.37113900018624283e-8f, r);
    float z = r * r;
    float sp = fmaf(z, -1.9515295891e-4f, 8.3321608736e-3f);
    sp = fmaf(z, sp, -1.6666654611e-1f);
    float sinr = fmaf(r * z, sp, r);
    float cp = fmaf(z, 2.443315711809948e-5f, -1.388731625493765e-3f);
    cp = fmaf(z, cp, 4.166664568298827e-2f);
    cp = fmaf(z, cp, -0.5f);
    float cosr = fmaf(z, cp, 1.0f);
    uint32_t res = (q & 1) ? __float_as_uint(sinr) : __float_as_uint(cosr);
    res ^= (uint32_t)((q + 1) & 2) << 30;
    res = (res + 0x1000u) & 0xFFFFE000u;           // tf32 rna
    return res;
}

__device__ __forceinline__ uint32_t smem_u32(const void* p) {
    uint32_t a;
    asm("{ .reg .u64 t; cvta.to.shared.u64 t, %1; cvt.u32.u64 %0, t; }" : "=r"(a) : "l"(p));
    return a;
}

#define MBAR_INIT(addr, cnt) \
    asm volatile("mbarrier.init.shared.b64 [%0], %1;" :: "r"(addr), "r"(cnt) : "memory")

#define MBAR_WAIT(addr, par) do {                                               \
    uint32_t _m = (addr); uint32_t _p = (par); uint32_t _d;                     \
    asm volatile("{\n\t.reg .pred p;\n\t"                                       \
        "mbarrier.try_wait.parity.acquire.cta.shared::cta.b64 p, [%1], %2;\n\t" \
        "selp.b32 %0, 1, 0, p;\n\t}"                                            \
        : "=r"(_d) : "r"(_m), "r"(_p) : "memory");                              \
    if (!_d) {                                                                  \
        asm volatile("{\n\t.reg .pred P1;\n\t"                                  \
            "WL_%=:\n\t"                                                        \
            "mbarrier.try_wait.parity.acquire.cta.shared::cta.b64 P1, [%0], %1, 0x989680;\n\t" \
            "@P1 bra.uni WD_%=;\n\t"                                            \
            "bra.uni WL_%=;\n\t"                                                \
            "WD_%=:\n\t}" :: "r"(_m), "r"(_p) : "memory");                      \
    }                                                                           \
} while (0)

__device__ __forceinline__ uint64_t make_desc_sw128(uint32_t addr) {
    const uint64_t base = (uint64_t(2) << 61) | (uint64_t(1) << 46) |
                          (uint64_t(64) << 32) | (uint64_t(1) << 16);
    return base | ((uint64_t)(addr >> 4) & 0x3FFF);
}

#define STS128(addr, a0, a1, a2, a3) \
    asm volatile("st.shared.v4.b32 [%0], {%1, %2, %3, %4};" \
                 :: "r"(addr), "r"(a0), "r"(a1), "r"(a2), "r"(a3) : "memory")

#if HAS_TCGEN05
__device__ __forceinline__ void mma_tf32_ss(uint32_t d_tmem, uint64_t a_desc,
                                            uint64_t b_desc, uint32_t idesc,
                                            uint32_t enable) {
    asm volatile(
        "{\n\t.reg .pred p;\n\t"
        "setp.ne.u32 p, %4, 0;\n\t"
        "tcgen05.mma.cta_group::1.kind::tf32 [%0], %1, %2, %3, p;\n\t}"
        :: "r"(d_tmem), "l"(a_desc), "l"(b_desc), "r"(idesc), "r"(enable)
        : "memory");
}
#endif

// ---------------------------------------------------------------------------
// Stage 0: round W to tf32, chunk-major + pre-swizzled.
// ---------------------------------------------------------------------------
__global__ __launch_bounds__(256) void roundw_kernel(const float* __restrict__ W) {
    int tid = blockIdx.x * 256 + threadIdx.x;
    int n    = tid >> 7;
    int rest = tid & 127;
    int c    = rest >> 3;
    int seg  = rest & 7;

    float4 v = *(const float4*)(W + (size_t)n * K_DIM + c * 32 + seg * 4);
    v.x = to_tf32(v.x); v.y = to_tf32(v.y); v.z = to_tf32(v.z); v.w = to_tf32(v.w);

    uint32_t byte_off = (uint32_t)n * 128 + seg * 16;
    uint32_t sw = byte_off ^ ((byte_off >> 3) & 0x70);
    *(float4*)((char*)g_W32 + (size_t)c * 65536 + sw) = v;
}

// ---------------------------------------------------------------------------
// Persistent fused kernel. Logical tile = (m-tile t, N-half nh), 1024 total.
// CTA bid statically owns tiles bid, bid+152, ...
// Tile decode: t = tile>>1, nh = tile&1, b = t>>6, q0 = 2*(t&63).
// A row a of tile = output row (b, (a>>1)*128 + q0 + (a&1)); cols nh*256+.
// Warps: 0-3 A-gen | 4-7 epilogue | 8 MMA | 9 B producer.
// TMEM halves double-buffered by tile parity p = local tile index & 1.
// ---------------------------------------------------------------------------
#define NCHUNK 16
#define NSA 4
#define NSB 4
#define SMEM_A0 1024
#define A_STAGE 16384
#define SMEM_B0 (SMEM_A0 + NSA * A_STAGE)     // 66560
#define B_SUB   32768
#define FUSED_SMEM (SMEM_B0 + NSB * B_SUB)    // 197632

#define OFF_FULLA 16      // 4 x 8B  (count 4: A warps)
#define OFF_DONEA 48      // 4 x 8B  (count 1: MMA commit)
#define OFF_FULLB 80      // 4 x 8B  (count 1: expect_tx)
#define OFF_DONEB 112     // 4 x 8B  (count 1: MMA commit)
#define OFF_FINAL 144     // 2 x 8B  (count 1: MMA commit per tile)
#define OFF_EPIFR 160     // 2 x 8B  (count 4: epi warps)

static constexpr uint32_t IDESC_N256 =
    (1u << 4)                // D = F32
    | (2u << 7)              // A = TF32
    | (2u << 10)             // B = TF32
    | ((256u / 8u) << 17)    // N = 256
    | ((128u / 16u) << 24);  // M = 128

extern "C" __global__ void __launch_bounds__(320, 1)
fused_kernel(const float* __restrict__ x, const float* __restrict__ theta,
             float* __restrict__ C) {
#if HAS_TCGEN05
    extern __shared__ char smem[];
    uint32_t smem_base = smem_u32(smem);
    int tid = threadIdx.x;
    int wid = tid >> 5;
    int lid = tid & 31;
    int bid = blockIdx.x;
    int ntiles = (NTILE - bid + GRID_P - 1) / GRID_P;   // 6 or 7

    uint32_t fullA = smem_base + OFF_FULLA;
    uint32_t doneA = smem_base + OFF_DONEA;
    uint32_t fullB = smem_base + OFF_FULLB;
    uint32_t doneB = smem_base + OFF_DONEB;
    uint32_t finb  = smem_base + OFF_FINAL;
    uint32_t epifr = smem_base + OFF_EPIFR;

    if (tid == 0) {
        for (int s = 0; s < NSA; s++) { MBAR_INIT(fullA + 8 * s, 4); MBAR_INIT(doneA + 8 * s, 1); }
        for (int s = 0; s < NSB; s++) { MBAR_INIT(fullB + 8 * s, 1); MBAR_INIT(doneB + 8 * s, 1); }
        for (int s = 0; s < 2;  s++) { MBAR_INIT(finb + 8 * s, 1);  MBAR_INIT(epifr + 8 * s, 4); }
    }
    if (wid == 8) {
        asm volatile("tcgen05.alloc.cta_group::1.sync.aligned.shared::cta.b32 [%0], %1;"
                     :: "r"(smem_base), "r"(512u) : "memory");
        asm volatile("tcgen05.relinquish_alloc_permit.cta_group::1.sync.aligned;");
    }
    __syncthreads();
    uint32_t tmem;
    asm volatile("ld.shared.b32 %0, [%1];" : "=r"(tmem) : "r"(smem_base));

    if (wid < 4) {
        // ============ A-gen warps: 128 threads, 32 cos/thread/chunk ========
        int j  = wid;               // x-row tag 0..3
        int wh = lid & 1;
        float tha = __ldg(theta + wh * 4 + 0);
        float thb = __ldg(theta + wh * 4 + 1);
        float thc = __ldg(theta + wh * 4 + 2);
        float thd = __ldg(theta + wh * 4 + 3);
        uint32_t koff = (uint32_t)(j * 32 + wh * 16);

        for (int k = 0; k < ntiles; k++) {
            int tile = bid + GRID_P * k;
            int t = tile >> 1;
            int b = t >> 6;
            int q0 = (t & 63) << 1;
            const float* xb = x + ((size_t)b << 22);
            for (int i = 0; i < NCHUNK; i++) {
                // coalesced loads: rows 64*(q0+dq)+4i+j, dq in {0,1}
                float4 xv[2][4];
#pragma unroll
                for (int dq = 0; dq < 2; dq++) {
                    const float* xp = xb + (size_t)(64 * (q0 + dq) + 4 * i + j) * E_DIM + lid * 4;
                    xv[dq][0] = *(const float4*)(xp);
                    xv[dq][1] = *(const float4*)(xp + 128);
                    xv[dq][2] = *(const float4*)(xp + 256);
                    xv[dq][3] = *(const float4*)(xp + 384);
                }
                int gch = k * NCHUNK + i;
                int st = gch & 3;
                if (gch >= NSA) MBAR_WAIT(doneA + 8 * st, ((gch - NSA) >> 2) & 1);
                uint32_t ast = smem_base + SMEM_A0 + st * A_STAGE;
#pragma unroll
                for (int dq = 0; dq < 2; dq++) {
#pragma unroll
                    for (int u = 0; u < 4; u++) {
                        uint32_t v0 = cos_tf32_bits(xv[dq][u].x + tha);
                        uint32_t v1 = cos_tf32_bits(xv[dq][u].y + thb);
                        uint32_t v2 = cos_tf32_bits(xv[dq][u].z + thc);
                        uint32_t v3 = cos_tf32_bits(xv[dq][u].w + thd);
                        int a = ((lid + 32 * u) & ~1) + dq;
                        uint32_t addr = ast + (uint32_t)a * 128 +
                                        (koff ^ (uint32_t)((a & 7) * 16));
                        STS128(addr, v0, v1, v2, v3);
                    }
                }
                asm volatile("fence.proxy.async.shared::cta;" ::: "memory");
                __syncwarp();
                if (lid == 0)
                    asm volatile("mbarrier.arrive.shared.b64 _, [%0];"
                                 :: "r"(fullA + 8 * st) : "memory");
            }
        }
    } else if (wid < 8) {
        // ============ epilogue warps: drain TMEM half p while other fills ==
        int row = (wid - 4) * 32 + lid;
        for (int k = 0; k < ntiles; k++) {
            int tile = bid + GRID_P * k;
            int t = tile >> 1;
            int nh = tile & 1;
            int b = t >> 6;
            int q0 = (t & 63) << 1;
            int p = k & 1;
            MBAR_WAIT(finb + 8 * p, (k >> 1) & 1);
            asm volatile("tcgen05.fence::after_thread_sync;" ::: "memory");
            int crow = (b << 13) + ((row >> 1) << 7) + q0 + (row & 1);
            float* Crow = C + (size_t)crow * N_DIM + nh * 256;
#pragma unroll
            for (int c = 0; c < 8; c++) {
                uint32_t d[32];
                asm volatile(
                    "tcgen05.ld.sync.aligned.32x32b.x32.b32 "
                    "{%0, %1, %2, %3, %4, %5, %6, %7, "
                    " %8, %9, %10, %11, %12, %13, %14, %15, "
                    " %16, %17, %18, %19, %20, %21, %22, %23, "
                    " %24, %25, %26, %27, %28, %29, %30, %31}, [%32];"
                    : "=r"(d[0]), "=r"(d[1]), "=r"(d[2]), "=r"(d[3]),
                      "=r"(d[4]), "=r"(d[5]), "=r"(d[6]), "=r"(d[7]),
                      "=r"(d[8]), "=r"(d[9]), "=r"(d[10]), "=r"(d[11]),
                      "=r"(d[12]), "=r"(d[13]), "=r"(d[14]), "=r"(d[15]),
                      "=r"(d[16]), "=r"(d[17]), "=r"(d[18]), "=r"(d[19]),
                      "=r"(d[20]), "=r"(d[21]), "=r"(d[22]), "=r"(d[23]),
                      "=r"(d[24]), "=r"(d[25]), "=r"(d[26]), "=r"(d[27]),
                      "=r"(d[28]), "=r"(d[29]), "=r"(d[30]), "=r"(d[31])
                    : "r"(tmem + p * 256 + 32 * c));
                asm volatile("tcgen05.wait::ld.sync.aligned;" ::: "memory");
#pragma unroll
                for (int jj = 0; jj < 8; jj++) {
                    float4 o = make_float4(__uint_as_float(d[4 * jj + 0]),
                                           __uint_as_float(d[4 * jj + 1]),
                                           __uint_as_float(d[4 * jj + 2]),
                                           __uint_as_float(d[4 * jj + 3]));
                    *(float4*)(Crow + 32 * c + 4 * jj) = o;
                }
            }
            asm volatile("tcgen05.fence::before_thread_sync;" ::: "memory");
            __syncwarp();
            if (lid == 0)
                asm volatile("mbarrier.arrive.shared.b64 _, [%0];"
                             :: "r"(epifr + 8 * p) : "memory");
        }
    } else if (wid == 8) {
        // ============ MMA warp ============
        for (int k = 0; k < ntiles; k++) {
            int p = k & 1;
            if (k >= 2) MBAR_WAIT(epifr + 8 * p, ((k - 2) >> 1) & 1);
            for (int i = 0; i < NCHUNK; i++) {
                int gch = k * NCHUNK + i;
                int st = gch & 3;
                int ph = (gch >> 2) & 1;
                MBAR_WAIT(fullA + 8 * st, ph);
                MBAR_WAIT(fullB + 8 * st, ph);
                asm volatile("fence.proxy.async.shared::cta;" ::: "memory");
                if (lid == 0) {
                    uint64_t ad = make_desc_sw128(smem_base + SMEM_A0 + st * A_STAGE);
                    uint64_t bd = make_desc_sw128(smem_base + SMEM_B0 + st * B_SUB);
#pragma unroll
                    for (int kk = 0; kk < 4; kk++) {
                        uint32_t en = (i | kk) != 0;
                        mma_tf32_ss(tmem + p * 256, ad + 2 * kk, bd + 2 * kk,
                                    IDESC_N256, en);
                    }
                    asm volatile(
                        "tcgen05.commit.cta_group::1.mbarrier::arrive::one.shared::cluster.b64 [%0];"
                        :: "r"(doneA + 8 * st) : "memory");
                    asm volatile(
                        "tcgen05.commit.cta_group::1.mbarrier::arrive::one.shared::cluster.b64 [%0];"
                        :: "r"(doneB + 8 * st) : "memory");
                }
            }
            if (lid == 0)
                asm volatile(
                    "tcgen05.commit.cta_group::1.mbarrier::arrive::one.shared::cluster.b64 [%0];"
                    :: "r"(finb + 8 * p) : "memory");
        }
    } else {
        // ============ B producer warp ============
        for (int k = 0; k < ntiles; k++) {
            int nh = (bid + GRID_P * k) & 1;
            for (int i = 0; i < NCHUNK; i++) {
                int gch = k * NCHUNK + i;
                int st = gch & 3;
                if (gch >= NSB) MBAR_WAIT(doneB + 8 * st, ((gch - NSB) >> 2) & 1);
                if (lid == 0) {
                    uint32_t bar = fullB + 8 * st;
                    asm volatile("mbarrier.arrive.expect_tx.shared::cta.b64 _, [%0], %1;"
                                 :: "r"(bar), "r"((uint32_t)B_SUB) : "memory");
                    const char* src = (const char*)g_W32 +
                                      (size_t)i * 65536 + (size_t)nh * B_SUB;
                    uint32_t dst = smem_base + SMEM_B0 + st * B_SUB;
                    asm volatile(
                        "cp.async.bulk.shared::cta.global.mbarrier::complete_tx::bytes "
                        "[%0], [%1], %2, [%3];"
                        :: "r"(dst), "l"(src), "r"((uint32_t)B_SUB), "r"(bar)
                        : "memory");
                }
            }
        }
    }

    __syncthreads();
    if (wid == 8) {
        asm volatile("tcgen05.dealloc.cta_group::1.sync.aligned.b32 %0, %1;"
                     :: "r"(tmem), "r"(512u));
    }
#else
    // Correct SIMT fallback (never selected on GB300). Same math + mapping.
    int bid = blockIdx.x;
    for (int tile = bid; tile < NTILE; tile += GRID_P) {
        int t = tile >> 1;
        int nh = tile & 1;
        int b = t >> 6;
        int q0 = (t & 63) << 1;
        int n0 = nh << 8;
        for (int idx = threadIdx.x; idx < 128 * 256; idx += 320) {
            int a = idx >> 8, n = idx & 255;
            int h = a >> 1;
            int q = q0 + (a & 1);
            float acc = 0.0f;
            for (int kk = 0; kk < K_DIM; kk++) {
                int sl = kk >> 3, w = kk & 7;
                float xv = x[(size_t)b * SE_DIM + (size_t)(64 * q + sl) * E_DIM + 8 * h + w];
                float av = __uint_as_float(cos_tf32_bits(xv + theta[w]));
                int c = kk >> 5, kc = kk & 31;
                uint32_t byte_off = (uint32_t)(n0 + n) * 128 + kc * 4;
                uint32_t sw = byte_off ^ ((byte_off >> 3) & 0x70);
                float wv = *(const float*)((const char*)g_W32 + (size_t)c * 65536 + sw);
                acc = fmaf(av, wv, acc);
            }
            C[(size_t)((b << 13) + (h << 7) + q) * N_DIM + n0 + n] = acc;
        }
    }
#endif
}

// ---------------------------------------------------------------------------
extern "C" void kernel_launch(void* const* d_in, const int* in_sizes, int n_in,
                              void* d_out, int out_size) {
    const float* x     = (const float*)d_in[0];
    const float* theta = (const float*)d_in[1];
    const float* W     = (const float*)d_in[2];
    float* y = (float*)d_out;

    static bool attr_done = false;
    if (!attr_done) {
        cudaFuncSetAttribute(fused_kernel,
                             cudaFuncAttributeMaxDynamicSharedMemorySize, FUSED_SMEM);
        attr_done = true;
    }

    roundw_kernel<<<256, 256>>>(W);
    fused_kernel<<<GRID_P, 320, FUSED_SMEM>>>(x, theta, y);
}

// round 14
// speedup vs baseline: 1.6908x; 1.6908x over previous
#include <cuda_runtime.h>
#include <cstdint>

#define S_DIM 8192
#define E_DIM 512
#define B_DIM 8
#define SE_DIM (S_DIM * E_DIM)
#define M_TOTAL 65536
#define K_DIM 512
#define N_DIM 512

#if defined(__CUDA_ARCH_FEAT_SM103_ALL) || defined(__CUDA_ARCH_FEAT_SM100_ALL) || \
    defined(__CUDA_ARCH_FEAT_SM101_ALL) || defined(__CUDA_ARCH_FEAT_SM110_ALL)
#define HAS_TCGEN05 1
#else
#define HAS_TCGEN05 0
#endif

// W scratch, CHUNK-MAJOR + PRE-SWIZZLED:
//   g_W32 byte (c*65536 + sw128(n*128 + j*4)) = tf32(W[n][c*32 + j])
__device__ float g_W32[(size_t)N_DIM * K_DIM];

// ---------------------------------------------------------------------------
__device__ __forceinline__ float to_tf32(float v) {
    float r;
    asm("cvt.rna.tf32.f32 %0, %1;" : "=f"(r) : "f"(v));
    return r;
}

// XU-free cos + tf32 rounding (fma/alu pipes only). Valid for |t| < ~1e5.
__device__ __forceinline__ uint32_t cos_tf32_bits(float t) {
    const float MAGIC = 12582912.0f;               // 1.5 * 2^23
    float g = fmaf(t, 0.63661977236758134f, MAGIC);
    int q = __float_as_int(g);
    float qf = g - MAGIC;
    float r = fmaf(qf, -1.57079637050628662109375f, t);
    r = fmaf(qf, 4.37113900018624283e-8f, r);
    float z = r * r;
    float sp = fmaf(z, -1.9515295891e-4f, 8.3321608736e-3f);
    sp = fmaf(z, sp, -1.6666654611e-1f);
    float sinr = fmaf(r * z, sp, r);
    float cp = fmaf(z, 2.443315711809948e-5f, -1.388731625493765e-3f);
    cp = fmaf(z, cp, 4.166664568298827e-2f);
    cp = fmaf(z, cp, -0.5f);
    float cosr = fmaf(z, cp, 1.0f);
    uint32_t res = (q & 1) ? __float_as_uint(sinr) : __float_as_uint(cosr);
    res ^= (uint32_t)((q + 1) & 2) << 30;
    res = (res + 0x1000u) & 0xFFFFE000u;           // tf32 rna
    return res;
}

__device__ __forceinline__ uint32_t smem_u32(const void* p) {
    uint32_t a;
    asm("{ .reg .u64 t; cvta.to.shared.u64 t, %1; cvt.u32.u64 %0, t; }" : "=r"(a) : "l"(p));
    return a;
}

#define MBAR_INIT(addr, cnt) \
    asm volatile("mbarrier.init.shared.b64 [%0], %1;" :: "r"(addr), "r"(cnt) : "memory")

#define MBAR_WAIT(addr, par) do {                                               \
    uint32_t _m = (addr); uint32_t _p = (par); uint32_t _d;                     \
    asm volatile("{\n\t.reg .pred p;\n\t"                                       \
        "mbarrier.try_wait.parity.acquire.cta.shared::cta.b64 p, [%1], %2;\n\t" \
        "selp.b32 %0, 1, 0, p;\n\t}"                                            \
        : "=r"(_d) : "r"(_m), "r"(_p) : "memory");                              \
    if (!_d) {                                                                  \
        asm volatile("{\n\t.reg .pred P1;\n\t"                                  \
            "WL_%=:\n\t"                                                        \
            "mbarrier.try_wait.parity.acquire.cta.shared::cta.b64 P1, [%0], %1, 0x989680;\n\t" \
            "@P1 bra.uni WD_%=;\n\t"                                            \
            "bra.uni WL_%=;\n\t"                                                \
            "WD_%=:\n\t}" :: "r"(_m), "r"(_p) : "memory");                      \
    }                                                                           \
} while (0)

__device__ __forceinline__ uint64_t make_desc_sw128(uint32_t addr) {
    const uint64_t base = (uint64_t(2) << 61) | (uint64_t(1) << 46) |
                          (uint64_t(64) << 32) | (uint64_t(1) << 16);
    return base | ((uint64_t)(addr >> 4) & 0x3FFF);
}

#define STS128(addr, a0, a1, a2, a3) \
    asm volatile("st.shared.v4.b32 [%0], {%1, %2, %3, %4};" \
                 :: "r"(addr), "r"(a0), "r"(a1), "r"(a2), "r"(a3) : "memory")

#define LDS128(r0, r1, r2, r3, addr) \
    asm volatile("ld.shared.v4.b32 {%0, %1, %2, %3}, [%4];" \
                 : "=r"(r0), "=r"(r1), "=r"(r2), "=r"(r3) : "r"(addr))

#if HAS_TCGEN05
__device__ __forceinline__ void mma_tf32_ss(uint32_t d_tmem, uint64_t a_desc,
                                            uint64_t b_desc, uint32_t idesc,
                                            uint32_t enable) {
    asm volatile(
        "{\n\t.reg .pred p;\n\t"
        "setp.ne.u32 p, %4, 0;\n\t"
        "tcgen05.mma.cta_group::1.kind::tf32 [%0], %1, %2, %3, p;\n\t}"
        :: "r"(d_tmem), "l"(a_desc), "l"(b_desc), "r"(idesc), "r"(enable)
        : "memory");
}

__device__ __forceinline__ void bulk_g2s(uint32_t dst, const void* src,
                                         uint32_t bytes, uint32_t bar) {
    asm volatile(
        "cp.async.bulk.shared::cta.global.mbarrier::complete_tx::bytes "
        "[%0], [%1], %2, [%3];"
        :: "r"(dst), "l"(src), "r"(bytes), "r"(bar) : "memory");
}
#endif

// ---------------------------------------------------------------------------
// Stage 0: round W to tf32, chunk-major + pre-swizzled.
// ---------------------------------------------------------------------------
__global__ __launch_bounds__(256) void roundw_kernel(const float* __restrict__ W) {
    int tid = blockIdx.x * 256 + threadIdx.x;
    int n    = tid >> 7;
    int rest = tid & 127;
    int c    = rest >> 3;
    int seg  = rest & 7;

    float4 v = *(const float4*)(W + (size_t)n * K_DIM + c * 32 + seg * 4);
    v.x = to_tf32(v.x); v.y = to_tf32(v.y); v.z = to_tf32(v.z); v.w = to_tf32(v.w);

    uint32_t byte_off = (uint32_t)n * 128 + seg * 16;
    uint32_t sw = byte_off ^ ((byte_off >> 3) & 0x70);
    *(float4*)((char*)g_W32 + (size_t)c * 65536 + sw) = v;
}

// ---------------------------------------------------------------------------
// Fused kernel, coalesced-x tiling + BULK x staging.
// Tile t: b = t>>6, q0 = 2*(t&63). A row a = output row (b, (a>>1)*128+q0+(a&1)).
// Chunk i x footprint = 2 contiguous 8KB blocks (rows 64(q0+dq)+4i..+3).
//   warps 0-7 : LDS x + cos + A STS (3-stage ring) + epilogue
//   warp 8    : MMA issue, commits doneA/doneB/final
//   warp 9    : bulk producer for BOTH x (3-stage, 16KB) and B (2-stage, 64KB)
// ---------------------------------------------------------------------------
#define NCHUNK 16
#define NSA 3
#define NSX 3
#define NSB 2
#define SMEM_A0 1024
#define A_STAGE 16384
#define SMEM_X0 (SMEM_A0 + NSA * A_STAGE)      // 50176
#define X_STAGE 16384
#define SMEM_B0 (SMEM_X0 + NSX * X_STAGE)      // 99328
#define B_STAGE 65536
#define FUSED_SMEM (SMEM_B0 + NSB * B_STAGE)   // 230400

#define OFF_FULLA 16      // 3 x 8B (count 8)
#define OFF_DONEA 40      // 3 x 8B (count 1, MMA commit)
#define OFF_XFULL 64      // 3 x 8B (count 1, expect_tx)
#define OFF_XFREE 88      // 3 x 8B (count 8)
#define OFF_FULLB 112     // 2 x 8B (count 1, expect_tx)
#define OFF_DONEB 128     // 2 x 8B (count 1, MMA commit)
#define OFF_FINAL 144     // 1 x 8B

static constexpr uint32_t IDESC_N256 =
    (1u << 4)                // D = F32
    | (2u << 7)              // A = TF32
    | (2u << 10)             // B = TF32
    | ((256u / 8u) << 17)    // N = 256
    | ((128u / 16u) << 24);  // M = 128

extern "C" __global__ void __launch_bounds__(320, 1)
fused_kernel(const float* __restrict__ x, const float* __restrict__ theta,
             float* __restrict__ C) {
#if HAS_TCGEN05
    extern __shared__ char smem[];
    uint32_t smem_base = smem_u32(smem);
    int tid = threadIdx.x;
    int wid = tid >> 5;
    int lid = tid & 31;

    int t = blockIdx.x;
    int b = t >> 6;
    int q0 = (t & 63) << 1;

    uint32_t fullA = smem_base + OFF_FULLA;
    uint32_t doneA = smem_base + OFF_DONEA;
    uint32_t xfull = smem_base + OFF_XFULL;
    uint32_t xfree = smem_base + OFF_XFREE;
    uint32_t fullB = smem_base + OFF_FULLB;
    uint32_t doneB = smem_base + OFF_DONEB;
    uint32_t finb  = smem_base + OFF_FINAL;

    if (tid == 0) {
        for (int s = 0; s < NSA; s++) { MBAR_INIT(fullA + 8 * s, 8); MBAR_INIT(doneA + 8 * s, 1); }
        for (int s = 0; s < NSX; s++) { MBAR_INIT(xfull + 8 * s, 1); MBAR_INIT(xfree + 8 * s, 8); }
        for (int s = 0; s < NSB; s++) { MBAR_INIT(fullB + 8 * s, 1); MBAR_INIT(doneB + 8 * s, 1); }
        MBAR_INIT(finb, 1);
    }
    if (wid == 8) {
        asm volatile("tcgen05.alloc.cta_group::1.sync.aligned.shared::cta.b32 [%0], %1;"
                     :: "r"(smem_base), "r"(512u) : "memory");
        asm volatile("tcgen05.relinquish_alloc_permit.cta_group::1.sync.aligned;");
    }
    __syncthreads();
    uint32_t tmem;
    asm volatile("ld.shared.b32 %0, [%1];" : "=r"(tmem) : "r"(smem_base));

    if (wid < 8) {
        // ================= worker warps (256 threads) =================
        int dq = wid >> 2;          // 0..1
        int j  = wid & 3;           // 0..3
        int wh = lid & 1;
        float tha = __ldg(theta + wh * 4 + 0);
        float thb = __ldg(theta + wh * 4 + 1);
        float thc = __ldg(theta + wh * 4 + 2);
        float thd = __ldg(theta + wh * 4 + 3);
        uint32_t koff = (uint32_t)(j * 32 + wh * 16);
        // this warp's x row within a stage: (dq*4 + j) * 2048, lane at +lid*16
        uint32_t xrow = (uint32_t)((dq * 4 + j) * 2048 + lid * 16);

        for (int i = 0; i < NCHUNK; i++) {
            int st = i % 3;
            int f  = i / 3;

            MBAR_WAIT(xfull + 8 * st, f & 1);
            uint32_t xs = smem_base + SMEM_X0 + st * X_STAGE + xrow;
            uint32_t xr[4][4];
            LDS128(xr[0][0], xr[0][1], xr[0][2], xr[0][3], xs);
            LDS128(xr[1][0], xr[1][1], xr[1][2], xr[1][3], xs + 512);
            LDS128(xr[2][0], xr[2][1], xr[2][2], xr[2][3], xs + 1024);
            LDS128(xr[3][0], xr[3][1], xr[3][2], xr[3][3], xs + 1536);

            if (i >= NSA) MBAR_WAIT(doneA + 8 * st, (f - 1) & 1);

            uint32_t ast = smem_base + SMEM_A0 + st * A_STAGE;
#pragma unroll
            for (int u = 0; u < 4; u++) {
                uint32_t v0 = cos_tf32_bits(__uint_as_float(xr[u][0]) + tha);
                uint32_t v1 = cos_tf32_bits(__uint_as_float(xr[u][1]) + thb);
                uint32_t v2 = cos_tf32_bits(__uint_as_float(xr[u][2]) + thc);
                uint32_t v3 = cos_tf32_bits(__uint_as_float(xr[u][3]) + thd);
                int a = ((lid + 32 * u) & ~1) + dq;
                uint32_t addr = ast + (uint32_t)a * 128 +
                                (koff ^ (uint32_t)((a & 7) * 16));
                STS128(addr, v0, v1, v2, v3);
            }

            asm volatile("fence.proxy.async.shared::cta;" ::: "memory");
            __syncwarp();
            if (lid == 0) {
                asm volatile("mbarrier.arrive.shared.b64 _, [%0];"
                             :: "r"(fullA + 8 * st) : "memory");
                asm volatile("mbarrier.arrive.shared.b64 _, [%0];"
                             :: "r"(xfree + 8 * st) : "memory");
            }
        }

        // ================= epilogue =================
        MBAR_WAIT(finb, 0);
        asm volatile("tcgen05.fence::after_thread_sync;" ::: "memory");

        int row = (wid & 3) * 32 + lid;      // A-tile row a
        int c0 = (wid >= 4) ? 256 : 0;
        int crow = (b << 13) + ((row >> 1) << 7) + q0 + (row & 1);
        float* Crow = C + (size_t)crow * N_DIM + c0;
#pragma unroll
        for (int c = 0; c < 8; c++) {
            uint32_t d[32];
            asm volatile(
                "tcgen05.ld.sync.aligned.32x32b.x32.b32 "
                "{%0, %1, %2, %3, %4, %5, %6, %7, "
                " %8, %9, %10, %11, %12, %13, %14, %15, "
                " %16, %17, %18, %19, %20, %21, %22, %23, "
                " %24, %25, %26, %27, %28, %29, %30, %31}, [%32];"
                : "=r"(d[0]), "=r"(d[1]), "=r"(d[2]), "=r"(d[3]),
                  "=r"(d[4]), "=r"(d[5]), "=r"(d[6]), "=r"(d[7]),
                  "=r"(d[8]), "=r"(d[9]), "=r"(d[10]), "=r"(d[11]),
                  "=r"(d[12]), "=r"(d[13]), "=r"(d[14]), "=r"(d[15]),
                  "=r"(d[16]), "=r"(d[17]), "=r"(d[18]), "=r"(d[19]),
                  "=r"(d[20]), "=r"(d[21]), "=r"(d[22]), "=r"(d[23]),
                  "=r"(d[24]), "=r"(d[25]), "=r"(d[26]), "=r"(d[27]),
                  "=r"(d[28]), "=r"(d[29]), "=r"(d[30]), "=r"(d[31])
                : "r"(tmem + c0 + 32 * c));
            asm volatile("tcgen05.wait::ld.sync.aligned;" ::: "memory");
#pragma unroll
            for (int jj = 0; jj < 8; jj++) {
                float4 o = make_float4(__uint_as_float(d[4 * jj + 0]),
                                       __uint_as_float(d[4 * jj + 1]),
                                       __uint_as_float(d[4 * jj + 2]),
                                       __uint_as_float(d[4 * jj + 3]));
                *(float4*)(Crow + 32 * c + 4 * jj) = o;
            }
        }
        asm volatile("tcgen05.fence::before_thread_sync;" ::: "memory");
    } else if (wid == 8) {
        // ================= MMA warp =================
        for (int i = 0; i < NCHUNK; i++) {
            int st = i % 3;
            int f  = i / 3;
            int stB = i & 1;
            MBAR_WAIT(fullA + 8 * st, f & 1);
            MBAR_WAIT(fullB + 8 * stB, (i >> 1) & 1);
            asm volatile("fence.proxy.async.shared::cta;" ::: "memory");
            if (lid == 0) {
                uint64_t ad  = make_desc_sw128(smem_base + SMEM_A0 + st * A_STAGE);
                uint32_t bb  = smem_base + SMEM_B0 + stB * B_STAGE;
                uint64_t bd0 = make_desc_sw128(bb);
                uint64_t bd1 = make_desc_sw128(bb + 256 * 128);
#pragma unroll
                for (int k = 0; k < 4; k++) {
                    uint32_t en = (i | k) != 0;
                    mma_tf32_ss(tmem,       ad + 2 * k, bd0 + 2 * k, IDESC_N256, en);
                    mma_tf32_ss(tmem + 256, ad + 2 * k, bd1 + 2 * k, IDESC_N256, en);
                }
                asm volatile(
                    "tcgen05.commit.cta_group::1.mbarrier::arrive::one.shared::cluster.b64 [%0];"
                    :: "r"(doneA + 8 * st) : "memory");
                asm volatile(
                    "tcgen05.commit.cta_group::1.mbarrier::arrive::one.shared::cluster.b64 [%0];"
                    :: "r"(doneB + 8 * stB) : "memory");
            }
        }
        if (lid == 0)
            asm volatile(
                "tcgen05.commit.cta_group::1.mbarrier::arrive::one.shared::cluster.b64 [%0];"
                :: "r"(finb) : "memory");
    } else {
        // ================= bulk producer warp (wid == 9): x + B ==========
        const char* xbase = (const char*)(x + ((size_t)b << 22));
        for (int i = 0; i < NCHUNK; i++) {
            int st = i % 3;
            int f  = i / 3;
            int stB = i & 1;
            // ---- x: wait free slot, then 2 x 8KB bulk ----
            if (i >= NSX) MBAR_WAIT(xfree + 8 * st, (f - 1) & 1);
            if (lid == 0) {
                uint32_t bar = xfull + 8 * st;
                asm volatile("mbarrier.arrive.expect_tx.shared::cta.b64 _, [%0], %1;"
                             :: "r"(bar), "r"((uint32_t)X_STAGE) : "memory");
                uint32_t dst = smem_base + SMEM_X0 + st * X_STAGE;
                bulk_g2s(dst,        xbase + (size_t)(64 * q0 + 4 * i) * 2048,       8192, bar);
                bulk_g2s(dst + 8192, xbase + (size_t)(64 * (q0 + 1) + 4 * i) * 2048, 8192, bar);
            }
            // ---- B: wait free slot, then 64KB bulk ----
            if (i >= NSB) MBAR_WAIT(doneB + 8 * stB, ((i - NSB) >> 1) & 1);
            if (lid == 0) {
                uint32_t bar = fullB + 8 * stB;
                asm volatile("mbarrier.arrive.expect_tx.shared::cta.b64 _, [%0], %1;"
                             :: "r"(bar), "r"((uint32_t)B_STAGE) : "memory");
                bulk_g2s(smem_base + SMEM_B0 + stB * B_STAGE,
                         (const char*)g_W32 + (size_t)i * B_STAGE, B_STAGE, bar);
            }
        }
    }

    __syncthreads();
    if (wid == 8) {
        asm volatile("tcgen05.dealloc.cta_group::1.sync.aligned.b32 %0, %1;"
                     :: "r"(tmem), "r"(512u));
    }
#else
    // Correct SIMT fallback (never selected on GB300). Same math + mapping.
    int t = blockIdx.x;
    int b = t >> 6;
    int q0 = (t & 63) << 1;
    for (int idx = threadIdx.x; idx < 128 * N_DIM; idx += 320) {
        int a = idx >> 9, n = idx & 511;
        int h = a >> 1;
        int q = q0 + (a & 1);
        float acc = 0.0f;
        for (int k = 0; k < K_DIM; k++) {
            int sl = k >> 3, w = k & 7;
            float xv = x[(size_t)b * SE_DIM + (size_t)(64 * q + sl) * E_DIM + 8 * h + w];
            float av = __uint_as_float(cos_tf32_bits(xv + theta[w]));
            int c = k >> 5, kk = k & 31;
            uint32_t byte_off = (uint32_t)n * 128 + kk * 4;
            uint32_t sw = byte_off ^ ((byte_off >> 3) & 0x70);
            float wv = *(const float*)((const char*)g_W32 + (size_t)c * 65536 + sw);
            acc = fmaf(av, wv, acc);
        }
        C[(size_t)((b << 13) + (h << 7) + q) * N_DIM + n] = acc;
    }
#endif
}

// ---------------------------------------------------------------------------
extern "C" void kernel_launch(void* const* d_in, const int* in_sizes, int n_in,
                              void* d_out, int out_size) {
    const float* x     = (const float*)d_in[0];
    const float* theta = (const float*)d_in[1];
    const float* W     = (const float*)d_in[2];
    float* y = (float*)d_out;

    static bool attr_done = false;
    if (!attr_done) {
        cudaFuncSetAttribute(fused_kernel,
                             cudaFuncAttributeMaxDynamicSharedMemorySize, FUSED_SMEM);
        attr_done = true;
    }

    roundw_kernel<<<256, 256>>>(W);
    fused_kernel<<<512, 320, FUSED_SMEM>>>(x, theta, y);
}